// round 7
// baseline (speedup 1.0000x reference)
#include <cuda_runtime.h>

#define NB 8
#define NBATCH 64
#define SEQ 1024
#define DIM 64
#define UDIM 128
#define SIGDIM 4160   // 64 + 64*64
#define FSTR 12       // feature row stride (floats), 48B = 16B-aligned

// ---------------- device scratch (no allocations allowed) ----------------
__device__ float g_sig[NBATCH * SIGDIM];
__device__ float g_hacc[NBATCH * UDIM];
__device__ float g_skip[NBATCH * UDIM];
__device__ float g_wts[NBATCH * UDIM];

// ---------------- helpers ----------------
__device__ __forceinline__ float siluf(float x) { return x / (1.f + __expf(-x)); }
__device__ __forceinline__ float sigm(float x) { return 1.f / (1.f + __expf(-x)); }

// packed dual-lane fp32 FMA (sm_100+, only reachable via PTX)
__device__ __forceinline__ void ffma2(unsigned long long& acc,
                                      unsigned long long f,
                                      unsigned long long w) {
    asm("fma.rn.f32x2 %0, %1, %2, %0;" : "+l"(acc) : "l"(f), "l"(w));
}
// duplicate one fp32 into both lanes of a b64 operand
__device__ __forceinline__ unsigned long long dup2(float f) {
    unsigned long long d;
    unsigned int u = __float_as_uint(f);
    asm("mov.b64 %0, {%1, %1};" : "=l"(d) : "r"(u));
    return d;
}
// pack two fp32 into a b64 operand
__device__ __forceinline__ unsigned long long pk2(float a, float b) {
    unsigned long long d;
    unsigned int ua = __float_as_uint(a), ub = __float_as_uint(b);
    asm("mov.b64 %0, {%1, %2};" : "=l"(d) : "r"(ua), "r"(ub));
    return d;
}

// Cox-de Boor, order 3, uniform knots grid[i] = (i-3)*0.4 - 1, i=0..11 -> 8 bases
__device__ __forceinline__ void bspl8(float x, float* o) {
    float b[11];
#pragma unroll
    for (int i = 0; i < 11; i++) {
        float g0 = (i - 3) * 0.4f - 1.0f;
        float g1 = (i - 2) * 0.4f - 1.0f;
        b[i] = (x >= g0 && x < g1) ? 1.f : 0.f;
    }
#pragma unroll
    for (int p = 1; p <= 3; p++) {
        float inv = 1.f / (0.4f * (float)p);
#pragma unroll
        for (int i = 0; i + p < 11; i++) {
            float gi  = (i - 3) * 0.4f - 1.0f;
            float gip = (i + p - 2) * 0.4f - 1.0f;
            b[i] = (x - gi) * inv * b[i] + (gip - x) * inv * b[i + 1];
        }
    }
#pragma unroll
    for (int i = 0; i < 8; i++) o[i] = b[i];
}

// ---------------- K1: path signature (one block per batch) ----------------
// S2[i][j] = sum_t (P_t[i] + 0.5*u_t[i]) * u_t[j],  P = exclusive prefix of u
__global__ __launch_bounds__(256) void k_sig(const float* __restrict__ x,
                                             const float* __restrict__ tw) {
    __shared__ __align__(16) float Ush[64 * 68];
    __shared__ __align__(16) float Qsh[64 * 68];
    __shared__ float segsum[4][64];
    __shared__ float carry[64];

    const int b = blockIdx.x, tid = threadIdx.x;

    // zero the GRKAN accumulators (64 blocks * 256 threads == 16384 == 2*8192)
    {
        int g = b * 256 + tid;
        if (g < NBATCH * UDIM) g_hacc[g] = 0.f;
        else g_skip[g - NBATCH * UDIM] = 0.f;
    }

    const int d = tid & 63, seg = tid >> 6;
    if (tid < 64) carry[tid] = 0.f;

    unsigned long long acc2[4][2];
#pragma unroll
    for (int a = 0; a < 4; a++) { acc2[a][0] = 0ull; acc2[a][1] = 0ull; }

    const int i0 = (tid & 15) * 4;   // prefix index (S2 row)
    const int j0 = (tid >> 4) * 4;   // increment index (S2 col)
    const float* xb = x + (size_t)b * SEQ * DIM;

    for (int t0 = 0; t0 < SEQ - 1; t0 += 64) {
        const int T = min(64, (SEQ - 1) - t0);
        __syncthreads();

        for (int idx = tid; idx < T * 64; idx += 256) {
            int t = idx >> 6, dd = idx & 63;
            int gt = t0 + t;
            Ush[t * 68 + dd] = tw[gt + 1] * xb[(gt + 1) * DIM + dd]
                             - tw[gt]     * xb[gt * DIM + dd];
        }
        __syncthreads();

        const int ss = seg * 16;
        const int se = min(ss + 16, T);
        float ssum = 0.f;
        for (int t = ss; t < se; t++) ssum += Ush[t * 68 + d];
        segsum[seg][d] = ssum;
        __syncthreads();
        float off = carry[d];
        for (int s = 0; s < seg; s++) off += segsum[s][d];
        __syncthreads();
        float p = off;
        for (int t = ss; t < se; t++) {
            float u = Ush[t * 68 + d];
            Qsh[t * 68 + d] = p + 0.5f * u;
            p += u;
        }
        if (seg == 3) carry[d] = p;
        __syncthreads();

        // rank-1-accumulate with FFMA2: acc[i][j,j+1] += q[i]*(u[j],u[j+1])
        for (int k = 0; k < T; k++) {
            float4 q  = *(const float4*)&Qsh[k * 68 + i0];
            float4 u4 = *(const float4*)&Ush[k * 68 + j0];
            unsigned long long uxy = pk2(u4.x, u4.y);
            unsigned long long uzw = pk2(u4.z, u4.w);
            unsigned long long q0 = dup2(q.x), q1 = dup2(q.y),
                               q2 = dup2(q.z), q3 = dup2(q.w);
            ffma2(acc2[0][0], q0, uxy); ffma2(acc2[0][1], q0, uzw);
            ffma2(acc2[1][0], q1, uxy); ffma2(acc2[1][1], q1, uzw);
            ffma2(acc2[2][0], q2, uxy); ffma2(acc2[2][1], q2, uzw);
            ffma2(acc2[3][0], q3, uxy); ffma2(acc2[3][1], q3, uzw);
        }
    }
    __syncthreads();

    float* sb = g_sig + (size_t)b * SIGDIM;
#pragma unroll
    for (int a = 0; a < 4; a++) {
        float2 lo = *(float2*)&acc2[a][0];
        float2 hi = *(float2*)&acc2[a][1];
        float4 v = make_float4(lo.x, lo.y, hi.x, hi.y);
        *(float4*)&sb[64 + (i0 + a) * 64 + j0] = v;
    }
    if (tid < 64)
        sb[tid] = tw[SEQ - 1] * xb[(SEQ - 1) * DIM + tid] - tw[0] * xb[tid];
}

// ---------------- K2: GRKAN layer 1 + skip (FFMA2 + vector feature loads) ----------------
__global__ __launch_bounds__(256, 2) void k_grkan1(const float* __restrict__ g1b,
                                                   const float* __restrict__ g1s,
                                                   const float* __restrict__ skw) {
    __shared__ __align__(16) float st[64 * 33];       // sig tile [batch][32 inputs]
    __shared__ __align__(16) float fb[2 * 64 * FSTR]; // scalar feats [dp][batch][12]
    __shared__ __align__(16) float wb[2 * 10 * 128];  // weight rows [dp][k(0..9)][u]

    const int tid = threadIdx.x;
    const int in0 = blockIdx.x * 32;

    for (int idx = tid; idx < 64 * 32; idx += 256) {
        int bb = idx >> 5, i = idx & 31;
        st[bb * 33 + i] = g_sig[(size_t)bb * SIGDIM + in0 + i];
    }

    unsigned long long ah2[4][4], as2[4][4];
#pragma unroll
    for (int i = 0; i < 4; i++)
#pragma unroll
        for (int j = 0; j < 4; j++) { ah2[i][j] = 0ull; as2[i][j] = 0ull; }

    const int cg = tid & 15, rg = tid >> 4;
    const int c0 = cg * 8, r0 = rg * 4;

    for (int dl = 0; dl < 32; dl += 2) {
        __syncthreads();
        if (tid < 128) {
            int bb = tid & 63, dp = tid >> 6;
            float xv = st[bb * 33 + dl + dp];
            float f[12];
            f[0] = siluf(xv);
            bspl8(xv, f + 1);
            f[9] = xv;                 // raw value for skip path
            f[10] = 0.f; f[11] = 0.f;
            float* fr = &fb[(dp * 64 + bb) * FSTR];
            *(float4*)&fr[0] = *(float4*)&f[0];
            *(float4*)&fr[4] = *(float4*)&f[4];
            *(float4*)&fr[8] = *(float4*)&f[8];
        }
        for (int idx = tid; idx < 2560; idx += 256) {
            int c = idx & 127, row = idx >> 7;  // row = dp*10 + k
            int dp = row / 10, k = row - dp * 10;
            int in = in0 + dl + dp;
            float w;
            if (k == 0) w = g1b[in * UDIM + c];
            else if (k < 9) w = g1s[(in * NB + (k - 1)) * UDIM + c];
            else w = skw[in * UDIM + c];
            wb[row * 128 + c] = w;
        }
        __syncthreads();

#pragma unroll
        for (int dp = 0; dp < 2; dp++) {
#pragma unroll
            for (int g = 0; g < 2; g++) {  // k = 4g .. 4g+3
                ulonglong2 w0a, w0c, w1a, w1c, w2a, w2c, w3a, w3c;
                {
                    const float* wr0 = &wb[(dp * 10 + 4 * g + 0) * 128 + c0];
                    const float* wr1 = &wb[(dp * 10 + 4 * g + 1) * 128 + c0];
                    const float* wr2 = &wb[(dp * 10 + 4 * g + 2) * 128 + c0];
                    const float* wr3 = &wb[(dp * 10 + 4 * g + 3) * 128 + c0];
                    w0a = *(const ulonglong2*)wr0; w0c = *(const ulonglong2*)(wr0 + 4);
                    w1a = *(const ulonglong2*)wr1; w1c = *(const ulonglong2*)(wr1 + 4);
                    w2a = *(const ulonglong2*)wr2; w2c = *(const ulonglong2*)(wr2 + 4);
                    w3a = *(const ulonglong2*)wr3; w3c = *(const ulonglong2*)(wr3 + 4);
                }
#pragma unroll
                for (int i = 0; i < 4; i++) {
                    float4 f4 = *(const float4*)&fb[(dp * 64 + r0 + i) * FSTR + 4 * g];
                    unsigned long long fx = dup2(f4.x), fy = dup2(f4.y),
                                       fz = dup2(f4.z), fw = dup2(f4.w);
                    ffma2(ah2[i][0], fx, w0a.x); ffma2(ah2[i][1], fx, w0a.y);
                    ffma2(ah2[i][2], fx, w0c.x); ffma2(ah2[i][3], fx, w0c.y);
                    ffma2(ah2[i][0], fy, w1a.x); ffma2(ah2[i][1], fy, w1a.y);
                    ffma2(ah2[i][2], fy, w1c.x); ffma2(ah2[i][3], fy, w1c.y);
                    ffma2(ah2[i][0], fz, w2a.x); ffma2(ah2[i][1], fz, w2a.y);
                    ffma2(ah2[i][2], fz, w2c.x); ffma2(ah2[i][3], fz, w2c.y);
                    ffma2(ah2[i][0], fw, w3a.x); ffma2(ah2[i][1], fw, w3a.y);
                    ffma2(ah2[i][2], fw, w3c.x); ffma2(ah2[i][3], fw, w3c.y);
                }
            }
            {   // tail: k=8 (h path) and k=9 (raw -> skip path)
                const float* wr8 = &wb[(dp * 10 + 8) * 128 + c0];
                const float* wr9 = &wb[(dp * 10 + 9) * 128 + c0];
                ulonglong2 w8a = *(const ulonglong2*)wr8, w8c = *(const ulonglong2*)(wr8 + 4);
                ulonglong2 w9a = *(const ulonglong2*)wr9, w9c = *(const ulonglong2*)(wr9 + 4);
#pragma unroll
                for (int i = 0; i < 4; i++) {
                    float2 ft = *(const float2*)&fb[(dp * 64 + r0 + i) * FSTR + 8];
                    unsigned long long f8 = dup2(ft.x), f9 = dup2(ft.y);
                    ffma2(ah2[i][0], f8, w8a.x); ffma2(ah2[i][1], f8, w8a.y);
                    ffma2(ah2[i][2], f8, w8c.x); ffma2(ah2[i][3], f8, w8c.y);
                    ffma2(as2[i][0], f9, w9a.x); ffma2(as2[i][1], f9, w9a.y);
                    ffma2(as2[i][2], f9, w9c.x); ffma2(as2[i][3], f9, w9c.y);
                }
            }
        }
    }

#pragma unroll
    for (int i = 0; i < 4; i++)
#pragma unroll
        for (int j = 0; j < 4; j++) {
            float2 h = *(float2*)&ah2[i][j];
            float2 s = *(float2*)&as2[i][j];
            atomicAdd(&g_hacc[(r0 + i) * UDIM + c0 + 2 * j],     h.x);
            atomicAdd(&g_hacc[(r0 + i) * UDIM + c0 + 2 * j + 1], h.y);
            atomicAdd(&g_skip[(r0 + i) * UDIM + c0 + 2 * j],     s.x);
            atomicAdd(&g_skip[(r0 + i) * UDIM + c0 + 2 * j + 1], s.y);
        }
}

// ---------------- K3: GRKAN layer 2, gate, layernorm, softmax ----------------
__global__ __launch_bounds__(128) void k_grkan2(const float* __restrict__ g2b,
                                                const float* __restrict__ g2s,
                                                const float* __restrict__ gws,
                                                const float* __restrict__ gbs,
                                                const float* __restrict__ gwv,
                                                const float* __restrict__ gbv,
                                                const float* __restrict__ skb,
                                                const float* __restrict__ lng,
                                                const float* __restrict__ lnb) {
    __shared__ float f2[128 * 9];
    __shared__ float h2s[128];
    __shared__ float red[4];

    const int b = blockIdx.x, u = threadIdx.x;

    auto blocksum = [&](float v) -> float {
#pragma unroll
        for (int o = 16; o; o >>= 1) v += __shfl_xor_sync(0xffffffffu, v, o);
        __syncthreads();
        if ((threadIdx.x & 31) == 0) red[threadIdx.x >> 5] = v;
        __syncthreads();
        return red[0] + red[1] + red[2] + red[3];
    };
    auto blockmax = [&](float v) -> float {
#pragma unroll
        for (int o = 16; o; o >>= 1) v = fmaxf(v, __shfl_xor_sync(0xffffffffu, v, o));
        __syncthreads();
        if ((threadIdx.x & 31) == 0) red[threadIdx.x >> 5] = v;
        __syncthreads();
        return fmaxf(fmaxf(red[0], red[1]), fmaxf(red[2], red[3]));
    };

    float hv = g_hacc[b * UDIM + u];
    float sk = g_skip[b * UDIM + u] + skb[u];

    f2[u * 9] = siluf(hv);
    bspl8(hv, &f2[u * 9 + 1]);
    __syncthreads();

    float a0 = 0.f, a1 = 0.f, a2 = 0.f;
    for (int v = 0; v < 128; v++) {
        const float* fr = &f2[v * 9];
        a0 += fr[0] * g2b[v * UDIM + u];
#pragma unroll
        for (int k = 0; k < 4; k++) a1 += fr[1 + k] * g2s[(v * NB + k) * UDIM + u];
#pragma unroll
        for (int k = 4; k < 8; k++) a2 += fr[1 + k] * g2s[(v * NB + k) * UDIM + u];
    }
    float h2 = a0 + a1 + a2;
    h2s[u] = h2;
    __syncthreads();

    float gs = gbs[u], gv = gbv[u];
    for (int v = 0; v < 128; v++) {
        float hh = h2s[v];
        gs += hh * gws[v * UDIM + u];
        gv += hh * gwv[v * UDIM + u];
    }
    float pre = sk + sigm(gs) * gv;

    float s1 = blocksum(pre);
    float s2 = blocksum(pre * pre);
    float mu = s1 * (1.f / 128.f);
    float var = s2 * (1.f / 128.f) - mu * mu;
    float y = lng[u] * (pre - mu) * rsqrtf(var + 1e-3f) + lnb[u];

    float m = blockmax(y);
    float e = __expf(y - m);
    float se = blocksum(e);
    g_wts[b * UDIM + u] = e / se;
}

// ---------------- K4: main KAN (FFMA2 + vector feature loads) ----------------
__global__ __launch_bounds__(256, 2) void k_main(const float* __restrict__ x,
                                                 const float* __restrict__ tw,
                                                 const float* __restrict__ kb,
                                                 const float* __restrict__ ksp,
                                                 float* __restrict__ out) {
    __shared__ __align__(16) float xt[128 * 33];       // w = tw*x, 128 rows x 32-dim chunk
    __shared__ __align__(16) float fb[2 * 128 * FSTR]; // scalar feats [dp][row][12]
    __shared__ __align__(16) float wb[2 * 9 * 128];    // weights [dp][k][u]

    const int tid = threadIdx.x;
    const int row0 = blockIdx.x * 128;
    const int b = row0 >> 10;
    const int s0 = row0 & (SEQ - 1);

    unsigned long long acc2[8][4];
#pragma unroll
    for (int i = 0; i < 8; i++)
#pragma unroll
        for (int j = 0; j < 4; j++) acc2[i][j] = 0ull;

    const int cg = tid & 15, rg = tid >> 4;
    const int c0 = cg * 8, r0 = rg * 8;
    const int frow = tid & 127, fdp = tid >> 7;

    for (int dc = 0; dc < 2; dc++) {
        __syncthreads();  // xt consumers from previous chunk done
        for (int idx = tid; idx < 128 * 32; idx += 256) {
            int r = idx >> 5, dd = idx & 31;
            xt[r * 33 + dd] = tw[s0 + r] * x[(size_t)(row0 + r) * DIM + dc * 32 + dd];
        }

        for (int dl = 0; dl < 32; dl += 2) {
            __syncthreads();  // xt ready (first dl) / fb,wb consumption done (later)
            {   // features for dims (dl+0, dl+1): all 256 threads
                float xv = xt[frow * 33 + dl + fdp];
                float f[12];
                f[0] = siluf(xv);
                bspl8(xv, f + 1);
                f[9] = 0.f; f[10] = 0.f; f[11] = 0.f;
                float* fr = &fb[(fdp * 128 + frow) * FSTR];
                *(float4*)&fr[0] = *(float4*)&f[0];
                *(float4*)&fr[4] = *(float4*)&f[4];
                *(float4*)&fr[8] = *(float4*)&f[8];
            }
            // weights: 18 rows (dp*9+k) x 128 = 576 float4
            for (int idx = tid; idx < 576; idx += 256) {
                int row = idx >> 5, cq = (idx & 31) * 4;
                int dp = row / 9, k = row - dp * 9;
                int dg = dc * 32 + dl + dp;
                float4 w = (k == 0)
                    ? *(const float4*)&kb[dg * UDIM + cq]
                    : *(const float4*)&ksp[(dg * NB + k - 1) * UDIM + cq];
                *(float4*)&wb[row * 128 + cq] = w;
            }
            __syncthreads();

#pragma unroll
            for (int dp = 0; dp < 2; dp++) {
#pragma unroll
                for (int g = 0; g < 2; g++) {  // k = 4g .. 4g+3
                    ulonglong2 w0a, w0c, w1a, w1c, w2a, w2c, w3a, w3c;
                    {
                        const float* wr0 = &wb[(dp * 9 + 4 * g + 0) * 128 + c0];
                        const float* wr1 = &wb[(dp * 9 + 4 * g + 1) * 128 + c0];
                        const float* wr2 = &wb[(dp * 9 + 4 * g + 2) * 128 + c0];
                        const float* wr3 = &wb[(dp * 9 + 4 * g + 3) * 128 + c0];
                        w0a = *(const ulonglong2*)wr0; w0c = *(const ulonglong2*)(wr0 + 4);
                        w1a = *(const ulonglong2*)wr1; w1c = *(const ulonglong2*)(wr1 + 4);
                        w2a = *(const ulonglong2*)wr2; w2c = *(const ulonglong2*)(wr2 + 4);
                        w3a = *(const ulonglong2*)wr3; w3c = *(const ulonglong2*)(wr3 + 4);
                    }
#pragma unroll
                    for (int i = 0; i < 8; i++) {
                        float4 f4 = *(const float4*)&fb[(dp * 128 + r0 + i) * FSTR + 4 * g];
                        unsigned long long fx = dup2(f4.x), fy = dup2(f4.y),
                                           fz = dup2(f4.z), fw = dup2(f4.w);
                        ffma2(acc2[i][0], fx, w0a.x); ffma2(acc2[i][1], fx, w0a.y);
                        ffma2(acc2[i][2], fx, w0c.x); ffma2(acc2[i][3], fx, w0c.y);
                        ffma2(acc2[i][0], fy, w1a.x); ffma2(acc2[i][1], fy, w1a.y);
                        ffma2(acc2[i][2], fy, w1c.x); ffma2(acc2[i][3], fy, w1c.y);
                        ffma2(acc2[i][0], fz, w2a.x); ffma2(acc2[i][1], fz, w2a.y);
                        ffma2(acc2[i][2], fz, w2c.x); ffma2(acc2[i][3], fz, w2c.y);
                        ffma2(acc2[i][0], fw, w3a.x); ffma2(acc2[i][1], fw, w3a.y);
                        ffma2(acc2[i][2], fw, w3c.x); ffma2(acc2[i][3], fw, w3c.y);
                    }
                }
                {   // tail k = 8
                    const float* wr8 = &wb[(dp * 9 + 8) * 128 + c0];
                    ulonglong2 w8a = *(const ulonglong2*)wr8;
                    ulonglong2 w8c = *(const ulonglong2*)(wr8 + 4);
#pragma unroll
                    for (int i = 0; i < 8; i++) {
                        unsigned long long f8 =
                            dup2(fb[(dp * 128 + r0 + i) * FSTR + 8]);
                        ffma2(acc2[i][0], f8, w8a.x); ffma2(acc2[i][1], f8, w8a.y);
                        ffma2(acc2[i][2], f8, w8c.x); ffma2(acc2[i][3], f8, w8c.y);
                    }
                }
            }
        }
    }

    float wv[8];
#pragma unroll
    for (int j = 0; j < 8; j++) wv[j] = g_wts[b * UDIM + c0 + j];
#pragma unroll
    for (int i = 0; i < 8; i++) {
        int row = row0 + r0 + i;
        float2 a0 = *(float2*)&acc2[i][0];
        float2 a1 = *(float2*)&acc2[i][1];
        float2 a2 = *(float2*)&acc2[i][2];
        float2 a3 = *(float2*)&acc2[i][3];
        float4 o0 = make_float4(a0.x * wv[0], a0.y * wv[1], a1.x * wv[2], a1.y * wv[3]);
        float4 o1 = make_float4(a2.x * wv[4], a2.y * wv[5], a3.x * wv[6], a3.y * wv[7]);
        *(float4*)&out[(size_t)row * UDIM + c0] = o0;
        *(float4*)&out[(size_t)row * UDIM + c0 + 4] = o1;
    }
}

// ---------------- launch ----------------
extern "C" void kernel_launch(void* const* d_in, const int* in_sizes, int n_in,
                              void* d_out, int out_size) {
    const float* x   = (const float*)d_in[0];
    const float* tw  = (const float*)d_in[1];
    const float* kb  = (const float*)d_in[2];
    const float* ksp = (const float*)d_in[3];
    const float* g1b = (const float*)d_in[4];
    const float* g1s = (const float*)d_in[5];
    const float* g2b = (const float*)d_in[6];
    const float* g2s = (const float*)d_in[7];
    const float* skw = (const float*)d_in[8];
    const float* skb = (const float*)d_in[9];
    const float* gws = (const float*)d_in[10];
    const float* gbs = (const float*)d_in[11];
    const float* gwv = (const float*)d_in[12];
    const float* gbv = (const float*)d_in[13];
    const float* lng = (const float*)d_in[14];
    const float* lnb = (const float*)d_in[15];
    float* out = (float*)d_out;

    k_sig<<<NBATCH, 256>>>(x, tw);                 // signature + zero accumulators
    k_grkan1<<<130, 256>>>(g1b, g1s, skw);         // split-K layer-1 + skip (FFMA2)
    k_grkan2<<<NBATCH, 128>>>(g2b, g2s, gws, gbs, gwv, gbv, skb, lng, lnb);
    k_main<<<512, 256>>>(x, tw, kb, ksp, out);     // dominant KAN GEMM (FFMA2)
}

// round 8
// speedup vs baseline: 1.1977x; 1.1977x over previous
#include <cuda_runtime.h>

#define NB 8
#define NBATCH 64
#define SEQ 1024
#define DIM 64
#define UDIM 128
#define SIGDIM 4160   // 64 + 64*64
#define FSTR 12       // feature row stride (floats), 48B = 16B-aligned
#define NSPLIT 4      // k_sig sequence splits

// ---------------- device scratch (no allocations allowed) ----------------
__device__ float g_sig[NBATCH * SIGDIM];
__device__ float g_part[NBATCH * NSPLIT * SIGDIM];   // per-split partial signatures
__device__ float g_hacc[NBATCH * UDIM];
__device__ float g_skip[NBATCH * UDIM];
__device__ float g_wts[NBATCH * UDIM];

// ---------------- helpers ----------------
__device__ __forceinline__ float siluf(float x) { return x / (1.f + __expf(-x)); }
__device__ __forceinline__ float sigm(float x) { return 1.f / (1.f + __expf(-x)); }

// packed dual-lane fp32 FMA (sm_100+, only reachable via PTX)
__device__ __forceinline__ void ffma2(unsigned long long& acc,
                                      unsigned long long f,
                                      unsigned long long w) {
    asm("fma.rn.f32x2 %0, %1, %2, %0;" : "+l"(acc) : "l"(f), "l"(w));
}
__device__ __forceinline__ unsigned long long dup2(float f) {
    unsigned long long d;
    unsigned int u = __float_as_uint(f);
    asm("mov.b64 %0, {%1, %1};" : "=l"(d) : "r"(u));
    return d;
}
__device__ __forceinline__ unsigned long long pk2(float a, float b) {
    unsigned long long d;
    unsigned int ua = __float_as_uint(a), ub = __float_as_uint(b);
    asm("mov.b64 %0, {%1, %2};" : "=l"(d) : "r"(ua), "r"(ub));
    return d;
}

// Cox-de Boor, order 3, uniform knots grid[i] = (i-3)*0.4 - 1, i=0..11 -> 8 bases
__device__ __forceinline__ void bspl8(float x, float* o) {
    float b[11];
#pragma unroll
    for (int i = 0; i < 11; i++) {
        float g0 = (i - 3) * 0.4f - 1.0f;
        float g1 = (i - 2) * 0.4f - 1.0f;
        b[i] = (x >= g0 && x < g1) ? 1.f : 0.f;
    }
#pragma unroll
    for (int p = 1; p <= 3; p++) {
        float inv = 1.f / (0.4f * (float)p);
#pragma unroll
        for (int i = 0; i + p < 11; i++) {
            float gi  = (i - 3) * 0.4f - 1.0f;
            float gip = (i + p - 2) * 0.4f - 1.0f;
            b[i] = (x - gi) * inv * b[i] + (gip - x) * inv * b[i + 1];
        }
    }
#pragma unroll
    for (int i = 0; i < 8; i++) o[i] = b[i];
}

// ---------------- K1a: partial path signature over 1/NSPLIT of the sequence ----------
// For its t-range, computes local S1_p (= total increment sum) and
// S2_p[i][j] = sum_t (P_t[i] + 0.5 u_t[i]) u_t[j] with LOCAL exclusive prefix P.
__global__ __launch_bounds__(256) void k_sig_part(const float* __restrict__ x,
                                                  const float* __restrict__ tw) {
    __shared__ __align__(16) float Ush[64 * 68];
    __shared__ __align__(16) float Qsh[64 * 68];
    __shared__ float segsum[4][64];
    __shared__ float carry[64];

    const int b = blockIdx.x >> 2;
    const int part = blockIdx.x & 3;
    const int tid = threadIdx.x;

    const int tstart = part * 256;
    const int tend = min(tstart + 256, SEQ - 1);   // 1023 increments total

    const int d = tid & 63, seg = tid >> 6;
    if (tid < 64) carry[tid] = 0.f;

    unsigned long long acc2[4][2];
#pragma unroll
    for (int a = 0; a < 4; a++) { acc2[a][0] = 0ull; acc2[a][1] = 0ull; }

    const int i0 = (tid & 15) * 4;   // prefix index (S2 row)
    const int j0 = (tid >> 4) * 4;   // increment index (S2 col)
    const float* xb = x + (size_t)b * SEQ * DIM;

    for (int t0 = tstart; t0 < tend; t0 += 64) {
        const int T = min(64, tend - t0);
        __syncthreads();

        for (int idx = tid; idx < T * 64; idx += 256) {
            int t = idx >> 6, dd = idx & 63;
            int gt = t0 + t;
            Ush[t * 68 + dd] = tw[gt + 1] * xb[(gt + 1) * DIM + dd]
                             - tw[gt]     * xb[gt * DIM + dd];
        }
        __syncthreads();

        const int ss = seg * 16;
        const int se = min(ss + 16, T);
        float ssum = 0.f;
        for (int t = ss; t < se; t++) ssum += Ush[t * 68 + d];
        segsum[seg][d] = ssum;
        __syncthreads();
        float off = carry[d];
        for (int s = 0; s < seg; s++) off += segsum[s][d];
        __syncthreads();
        float p = off;
        for (int t = ss; t < se; t++) {
            float u = Ush[t * 68 + d];
            Qsh[t * 68 + d] = p + 0.5f * u;
            p += u;
        }
        if (seg == 3) carry[d] = p;
        __syncthreads();

        for (int k = 0; k < T; k++) {
            float4 q  = *(const float4*)&Qsh[k * 68 + i0];
            float4 u4 = *(const float4*)&Ush[k * 68 + j0];
            unsigned long long uxy = pk2(u4.x, u4.y);
            unsigned long long uzw = pk2(u4.z, u4.w);
            unsigned long long q0 = dup2(q.x), q1 = dup2(q.y),
                               q2 = dup2(q.z), q3 = dup2(q.w);
            ffma2(acc2[0][0], q0, uxy); ffma2(acc2[0][1], q0, uzw);
            ffma2(acc2[1][0], q1, uxy); ffma2(acc2[1][1], q1, uzw);
            ffma2(acc2[2][0], q2, uxy); ffma2(acc2[2][1], q2, uzw);
            ffma2(acc2[3][0], q3, uxy); ffma2(acc2[3][1], q3, uzw);
        }
    }
    __syncthreads();

    float* pb = g_part + (size_t)(b * NSPLIT + part) * SIGDIM;
#pragma unroll
    for (int a = 0; a < 4; a++) {
        float2 lo = *(float2*)&acc2[a][0];
        float2 hi = *(float2*)&acc2[a][1];
        float4 v = make_float4(lo.x, lo.y, hi.x, hi.y);
        *(float4*)&pb[64 + (i0 + a) * 64 + j0] = v;
    }
    if (tid < 64) pb[tid] = carry[tid];   // local S1_p = total increment sum of part
}

// ---------------- K1b: Chen combine of NSPLIT partials -> full signature ----------
// S1 = sum_p S1_p ;  S2 = sum_p ( S2_p + prefixS1_p (x) S1_p )
__global__ __launch_bounds__(256) void k_sig_combine() {
    __shared__ float s1[NSPLIT][64];
    __shared__ float pre[NSPLIT][64];

    const int b = blockIdx.x, tid = threadIdx.x;

    // zero the GRKAN accumulators (64 blocks * 256 threads == 2 * 8192)
    {
        int g = b * 256 + tid;
        if (g < NBATCH * UDIM) g_hacc[g] = 0.f;
        else g_skip[g - NBATCH * UDIM] = 0.f;
    }

    if (tid < 64) {
        float acc = 0.f;
#pragma unroll
        for (int p = 0; p < NSPLIT; p++) {
            float v = g_part[(size_t)(b * NSPLIT + p) * SIGDIM + tid];
            s1[p][tid] = v;
            pre[p][tid] = acc;   // exclusive prefix
            acc += v;
        }
        g_sig[(size_t)b * SIGDIM + tid] = acc;   // full S1
    }
    __syncthreads();

    const int i0 = (tid & 15) * 4;
    const int j0 = (tid >> 4) * 4;

    float acc[4][4];
#pragma unroll
    for (int a = 0; a < 4; a++)
#pragma unroll
        for (int c = 0; c < 4; c++) acc[a][c] = 0.f;

#pragma unroll
    for (int p = 0; p < NSPLIT; p++) {
        const float* s2p = g_part + (size_t)(b * NSPLIT + p) * SIGDIM + 64;
        float4 s1j = *(const float4*)&s1[p][j0];
#pragma unroll
        for (int a = 0; a < 4; a++) {
            float4 v = *(const float4*)&s2p[(i0 + a) * 64 + j0];
            float pi = pre[p][i0 + a];
            acc[a][0] += v.x + pi * s1j.x;
            acc[a][1] += v.y + pi * s1j.y;
            acc[a][2] += v.z + pi * s1j.z;
            acc[a][3] += v.w + pi * s1j.w;
        }
    }

    float* sb = g_sig + (size_t)b * SIGDIM;
#pragma unroll
    for (int a = 0; a < 4; a++) {
        float4 v = make_float4(acc[a][0], acc[a][1], acc[a][2], acc[a][3]);
        *(float4*)&sb[64 + (i0 + a) * 64 + j0] = v;
    }
}

// ---------------- K2: GRKAN layer 1 + skip (FFMA2 + vector feature loads) ----------------
__global__ __launch_bounds__(256, 2) void k_grkan1(const float* __restrict__ g1b,
                                                   const float* __restrict__ g1s,
                                                   const float* __restrict__ skw) {
    __shared__ __align__(16) float st[64 * 33];
    __shared__ __align__(16) float fb[2 * 64 * FSTR];
    __shared__ __align__(16) float wb[2 * 10 * 128];

    const int tid = threadIdx.x;
    const int in0 = blockIdx.x * 32;

    for (int idx = tid; idx < 64 * 32; idx += 256) {
        int bb = idx >> 5, i = idx & 31;
        st[bb * 33 + i] = g_sig[(size_t)bb * SIGDIM + in0 + i];
    }

    unsigned long long ah2[4][4], as2[4][4];
#pragma unroll
    for (int i = 0; i < 4; i++)
#pragma unroll
        for (int j = 0; j < 4; j++) { ah2[i][j] = 0ull; as2[i][j] = 0ull; }

    const int cg = tid & 15, rg = tid >> 4;
    const int c0 = cg * 8, r0 = rg * 4;

    for (int dl = 0; dl < 32; dl += 2) {
        __syncthreads();
        if (tid < 128) {
            int bb = tid & 63, dp = tid >> 6;
            float xv = st[bb * 33 + dl + dp];
            float f[12];
            f[0] = siluf(xv);
            bspl8(xv, f + 1);
            f[9] = xv;
            f[10] = 0.f; f[11] = 0.f;
            float* fr = &fb[(dp * 64 + bb) * FSTR];
            *(float4*)&fr[0] = *(float4*)&f[0];
            *(float4*)&fr[4] = *(float4*)&f[4];
            *(float4*)&fr[8] = *(float4*)&f[8];
        }
        for (int idx = tid; idx < 2560; idx += 256) {
            int c = idx & 127, row = idx >> 7;
            int dp = row / 10, k = row - dp * 10;
            int in = in0 + dl + dp;
            float w;
            if (k == 0) w = g1b[in * UDIM + c];
            else if (k < 9) w = g1s[(in * NB + (k - 1)) * UDIM + c];
            else w = skw[in * UDIM + c];
            wb[row * 128 + c] = w;
        }
        __syncthreads();

#pragma unroll
        for (int dp = 0; dp < 2; dp++) {
#pragma unroll
            for (int g = 0; g < 2; g++) {
                ulonglong2 w0a, w0c, w1a, w1c, w2a, w2c, w3a, w3c;
                {
                    const float* wr0 = &wb[(dp * 10 + 4 * g + 0) * 128 + c0];
                    const float* wr1 = &wb[(dp * 10 + 4 * g + 1) * 128 + c0];
                    const float* wr2 = &wb[(dp * 10 + 4 * g + 2) * 128 + c0];
                    const float* wr3 = &wb[(dp * 10 + 4 * g + 3) * 128 + c0];
                    w0a = *(const ulonglong2*)wr0; w0c = *(const ulonglong2*)(wr0 + 4);
                    w1a = *(const ulonglong2*)wr1; w1c = *(const ulonglong2*)(wr1 + 4);
                    w2a = *(const ulonglong2*)wr2; w2c = *(const ulonglong2*)(wr2 + 4);
                    w3a = *(const ulonglong2*)wr3; w3c = *(const ulonglong2*)(wr3 + 4);
                }
#pragma unroll
                for (int i = 0; i < 4; i++) {
                    float4 f4 = *(const float4*)&fb[(dp * 64 + r0 + i) * FSTR + 4 * g];
                    unsigned long long fx = dup2(f4.x), fy = dup2(f4.y),
                                       fz = dup2(f4.z), fw = dup2(f4.w);
                    ffma2(ah2[i][0], fx, w0a.x); ffma2(ah2[i][1], fx, w0a.y);
                    ffma2(ah2[i][2], fx, w0c.x); ffma2(ah2[i][3], fx, w0c.y);
                    ffma2(ah2[i][0], fy, w1a.x); ffma2(ah2[i][1], fy, w1a.y);
                    ffma2(ah2[i][2], fy, w1c.x); ffma2(ah2[i][3], fy, w1c.y);
                    ffma2(ah2[i][0], fz, w2a.x); ffma2(ah2[i][1], fz, w2a.y);
                    ffma2(ah2[i][2], fz, w2c.x); ffma2(ah2[i][3], fz, w2c.y);
                    ffma2(ah2[i][0], fw, w3a.x); ffma2(ah2[i][1], fw, w3a.y);
                    ffma2(ah2[i][2], fw, w3c.x); ffma2(ah2[i][3], fw, w3c.y);
                }
            }
            {
                const float* wr8 = &wb[(dp * 10 + 8) * 128 + c0];
                const float* wr9 = &wb[(dp * 10 + 9) * 128 + c0];
                ulonglong2 w8a = *(const ulonglong2*)wr8, w8c = *(const ulonglong2*)(wr8 + 4);
                ulonglong2 w9a = *(const ulonglong2*)wr9, w9c = *(const ulonglong2*)(wr9 + 4);
#pragma unroll
                for (int i = 0; i < 4; i++) {
                    float2 ft = *(const float2*)&fb[(dp * 64 + r0 + i) * FSTR + 8];
                    unsigned long long f8 = dup2(ft.x), f9 = dup2(ft.y);
                    ffma2(ah2[i][0], f8, w8a.x); ffma2(ah2[i][1], f8, w8a.y);
                    ffma2(ah2[i][2], f8, w8c.x); ffma2(ah2[i][3], f8, w8c.y);
                    ffma2(as2[i][0], f9, w9a.x); ffma2(as2[i][1], f9, w9a.y);
                    ffma2(as2[i][2], f9, w9c.x); ffma2(as2[i][3], f9, w9c.y);
                }
            }
        }
    }

#pragma unroll
    for (int i = 0; i < 4; i++)
#pragma unroll
        for (int j = 0; j < 4; j++) {
            float2 h = *(float2*)&ah2[i][j];
            float2 s = *(float2*)&as2[i][j];
            atomicAdd(&g_hacc[(r0 + i) * UDIM + c0 + 2 * j],     h.x);
            atomicAdd(&g_hacc[(r0 + i) * UDIM + c0 + 2 * j + 1], h.y);
            atomicAdd(&g_skip[(r0 + i) * UDIM + c0 + 2 * j],     s.x);
            atomicAdd(&g_skip[(r0 + i) * UDIM + c0 + 2 * j + 1], s.y);
        }
}

// ---------------- K3: GRKAN layer 2, gate, layernorm, softmax ----------------
__global__ __launch_bounds__(128) void k_grkan2(const float* __restrict__ g2b,
                                                const float* __restrict__ g2s,
                                                const float* __restrict__ gws,
                                                const float* __restrict__ gbs,
                                                const float* __restrict__ gwv,
                                                const float* __restrict__ gbv,
                                                const float* __restrict__ skb,
                                                const float* __restrict__ lng,
                                                const float* __restrict__ lnb) {
    __shared__ float f2[128 * 9];
    __shared__ float h2s[128];
    __shared__ float red[4];

    const int b = blockIdx.x, u = threadIdx.x;

    auto blocksum = [&](float v) -> float {
#pragma unroll
        for (int o = 16; o; o >>= 1) v += __shfl_xor_sync(0xffffffffu, v, o);
        __syncthreads();
        if ((threadIdx.x & 31) == 0) red[threadIdx.x >> 5] = v;
        __syncthreads();
        return red[0] + red[1] + red[2] + red[3];
    };
    auto blockmax = [&](float v) -> float {
#pragma unroll
        for (int o = 16; o; o >>= 1) v = fmaxf(v, __shfl_xor_sync(0xffffffffu, v, o));
        __syncthreads();
        if ((threadIdx.x & 31) == 0) red[threadIdx.x >> 5] = v;
        __syncthreads();
        return fmaxf(fmaxf(red[0], red[1]), fmaxf(red[2], red[3]));
    };

    float hv = g_hacc[b * UDIM + u];
    float sk = g_skip[b * UDIM + u] + skb[u];

    f2[u * 9] = siluf(hv);
    bspl8(hv, &f2[u * 9 + 1]);
    __syncthreads();

    float a0 = 0.f, a1 = 0.f, a2 = 0.f;
    for (int v = 0; v < 128; v++) {
        const float* fr = &f2[v * 9];
        a0 += fr[0] * g2b[v * UDIM + u];
#pragma unroll
        for (int k = 0; k < 4; k++) a1 += fr[1 + k] * g2s[(v * NB + k) * UDIM + u];
#pragma unroll
        for (int k = 4; k < 8; k++) a2 += fr[1 + k] * g2s[(v * NB + k) * UDIM + u];
    }
    float h2 = a0 + a1 + a2;
    h2s[u] = h2;
    __syncthreads();

    float gs = gbs[u], gv = gbv[u];
    for (int v = 0; v < 128; v++) {
        float hh = h2s[v];
        gs += hh * gws[v * UDIM + u];
        gv += hh * gwv[v * UDIM + u];
    }
    float pre = sk + sigm(gs) * gv;

    float s1 = blocksum(pre);
    float s2 = blocksum(pre * pre);
    float mu = s1 * (1.f / 128.f);
    float var = s2 * (1.f / 128.f) - mu * mu;
    float y = lng[u] * (pre - mu) * rsqrtf(var + 1e-3f) + lnb[u];

    float m = blockmax(y);
    float e = __expf(y - m);
    float se = blocksum(e);
    g_wts[b * UDIM + u] = e / se;
}

// ---------------- K4: main KAN (FFMA2, 8-dim group staging, dynamic smem) ----------------
// smem layout (floats): xt[128*33] | fb[8*128*FSTR] | wb[8*9*128]
#define SM_XT 0
#define SM_FB (128 * 33)                       // 4224
#define SM_WB (SM_FB + 8 * 128 * FSTR)         // 4224 + 12288 = 16512
#define SM_TOTF (SM_WB + 8 * 9 * 128)          // 16512 + 9216 = 25728 floats
#define SM_BYTES (SM_TOTF * 4)                 // 102912 bytes

__global__ __launch_bounds__(256, 2) void k_main(const float* __restrict__ x,
                                                 const float* __restrict__ tw,
                                                 const float* __restrict__ kb,
                                                 const float* __restrict__ ksp,
                                                 float* __restrict__ out) {
    extern __shared__ __align__(16) float smem[];
    float* xt = smem + SM_XT;   // w = tw*x, 128 rows x 32-dim chunk (stride 33)
    float* fb = smem + SM_FB;   // features [dim(8)][row(128)][FSTR]
    float* wb = smem + SM_WB;   // weights  [dim(8)*9 + k][128]

    const int tid = threadIdx.x;
    const int row0 = blockIdx.x * 128;
    const int b = row0 >> 10;
    const int s0 = row0 & (SEQ - 1);

    unsigned long long acc2[8][4];
#pragma unroll
    for (int i = 0; i < 8; i++)
#pragma unroll
        for (int j = 0; j < 4; j++) acc2[i][j] = 0ull;

    const int cg = tid & 15, rg = tid >> 4;
    const int c0 = cg * 8, r0 = rg * 8;

    for (int dc = 0; dc < 2; dc++) {
        __syncthreads();  // prior group's staging/compute fully done before xt overwrite
        for (int idx = tid; idx < 128 * 32; idx += 256) {
            int r = idx >> 5, dd = idx & 31;
            xt[r * 33 + dd] = tw[s0 + r] * x[(size_t)(row0 + r) * DIM + dc * 32 + dd];
        }

        for (int g8 = 0; g8 < 4; g8++) {        // 8 dims per staging group
            const int d0 = g8 * 8;
            __syncthreads();  // xt ready (g8=0) / fb,wb consumption done (later)

            // features: 128 rows x 8 dims, 4 bspl8 per thread
#pragma unroll
            for (int q = 0; q < 4; q++) {
                int idx = tid + q * 256;
                int dd = idx & 7, r = idx >> 3;
                float xv = xt[r * 33 + d0 + dd];
                float f[8];
                float* fr = &fb[(dd * 128 + r) * FSTR];
                float f0 = siluf(xv);
                bspl8(xv, f);
                float4 v0 = make_float4(f0, f[0], f[1], f[2]);
                float4 v1 = make_float4(f[3], f[4], f[5], f[6]);
                *(float4*)&fr[0] = v0;
                *(float4*)&fr[4] = v1;
                fr[8] = f[7];
            }
            // weights: 72 rows (dd*9+k) x 128 floats = 2304 float4, 9 per thread
#pragma unroll
            for (int q = 0; q < 9; q++) {
                int idx = tid + q * 256;
                int rowk = idx >> 5, cq = (idx & 31) * 4;
                int dd = rowk / 9, k = rowk - dd * 9;
                int dg = dc * 32 + d0 + dd;
                float4 w = (k == 0)
                    ? *(const float4*)&kb[dg * UDIM + cq]
                    : *(const float4*)&ksp[(dg * NB + k - 1) * UDIM + cq];
                *(float4*)&wb[rowk * 128 + cq] = w;
            }
            __syncthreads();

#pragma unroll 2
            for (int dd = 0; dd < 8; dd++) {
#pragma unroll
                for (int g = 0; g < 2; g++) {  // k = 4g .. 4g+3
                    ulonglong2 w0a, w0c, w1a, w1c, w2a, w2c, w3a, w3c;
                    {
                        const float* wr0 = &wb[(dd * 9 + 4 * g + 0) * 128 + c0];
                        const float* wr1 = &wb[(dd * 9 + 4 * g + 1) * 128 + c0];
                        const float* wr2 = &wb[(dd * 9 + 4 * g + 2) * 128 + c0];
                        const float* wr3 = &wb[(dd * 9 + 4 * g + 3) * 128 + c0];
                        w0a = *(const ulonglong2*)wr0; w0c = *(const ulonglong2*)(wr0 + 4);
                        w1a = *(const ulonglong2*)wr1; w1c = *(const ulonglong2*)(wr1 + 4);
                        w2a = *(const ulonglong2*)wr2; w2c = *(const ulonglong2*)(wr2 + 4);
                        w3a = *(const ulonglong2*)wr3; w3c = *(const ulonglong2*)(wr3 + 4);
                    }
#pragma unroll
                    for (int i = 0; i < 8; i++) {
                        float4 f4 = *(const float4*)&fb[(dd * 128 + r0 + i) * FSTR + 4 * g];
                        unsigned long long fx = dup2(f4.x), fy = dup2(f4.y),
                                           fz = dup2(f4.z), fw = dup2(f4.w);
                        ffma2(acc2[i][0], fx, w0a.x); ffma2(acc2[i][1], fx, w0a.y);
                        ffma2(acc2[i][2], fx, w0c.x); ffma2(acc2[i][3], fx, w0c.y);
                        ffma2(acc2[i][0], fy, w1a.x); ffma2(acc2[i][1], fy, w1a.y);
                        ffma2(acc2[i][2], fy, w1c.x); ffma2(acc2[i][3], fy, w1c.y);
                        ffma2(acc2[i][0], fz, w2a.x); ffma2(acc2[i][1], fz, w2a.y);
                        ffma2(acc2[i][2], fz, w2c.x); ffma2(acc2[i][3], fz, w2c.y);
                        ffma2(acc2[i][0], fw, w3a.x); ffma2(acc2[i][1], fw, w3a.y);
                        ffma2(acc2[i][2], fw, w3c.x); ffma2(acc2[i][3], fw, w3c.y);
                    }
                }
                {   // tail k = 8
                    const float* wr8 = &wb[(dd * 9 + 8) * 128 + c0];
                    ulonglong2 w8a = *(const ulonglong2*)wr8;
                    ulonglong2 w8c = *(const ulonglong2*)(wr8 + 4);
#pragma unroll
                    for (int i = 0; i < 8; i++) {
                        unsigned long long f8 =
                            dup2(fb[(dd * 128 + r0 + i) * FSTR + 8]);
                        ffma2(acc2[i][0], f8, w8a.x); ffma2(acc2[i][1], f8, w8a.y);
                        ffma2(acc2[i][2], f8, w8c.x); ffma2(acc2[i][3], f8, w8c.y);
                    }
                }
            }
        }
    }

    float wv[8];
#pragma unroll
    for (int j = 0; j < 8; j++) wv[j] = g_wts[b * UDIM + c0 + j];
#pragma unroll
    for (int i = 0; i < 8; i++) {
        int row = row0 + r0 + i;
        float2 a0 = *(float2*)&acc2[i][0];
        float2 a1 = *(float2*)&acc2[i][1];
        float2 a2 = *(float2*)&acc2[i][2];
        float2 a3 = *(float2*)&acc2[i][3];
        float4 o0 = make_float4(a0.x * wv[0], a0.y * wv[1], a1.x * wv[2], a1.y * wv[3]);
        float4 o1 = make_float4(a2.x * wv[4], a2.y * wv[5], a3.x * wv[6], a3.y * wv[7]);
        *(float4*)&out[(size_t)row * UDIM + c0] = o0;
        *(float4*)&out[(size_t)row * UDIM + c0 + 4] = o1;
    }
}

// ---------------- launch ----------------
extern "C" void kernel_launch(void* const* d_in, const int* in_sizes, int n_in,
                              void* d_out, int out_size) {
    const float* x   = (const float*)d_in[0];
    const float* tw  = (const float*)d_in[1];
    const float* kb  = (const float*)d_in[2];
    const float* ksp = (const float*)d_in[3];
    const float* g1b = (const float*)d_in[4];
    const float* g1s = (const float*)d_in[5];
    const float* g2b = (const float*)d_in[6];
    const float* g2s = (const float*)d_in[7];
    const float* skw = (const float*)d_in[8];
    const float* skb = (const float*)d_in[9];
    const float* gws = (const float*)d_in[10];
    const float* gbs = (const float*)d_in[11];
    const float* gwv = (const float*)d_in[12];
    const float* gbv = (const float*)d_in[13];
    const float* lng = (const float*)d_in[14];
    const float* lnb = (const float*)d_in[15];
    float* out = (float*)d_out;

    cudaFuncSetAttribute(k_main, cudaFuncAttributeMaxDynamicSharedMemorySize, SM_BYTES);

    k_sig_part<<<NBATCH * NSPLIT, 256>>>(x, tw);   // split signature partials
    k_sig_combine<<<NBATCH, 256>>>();              // Chen combine + zero accumulators
    k_grkan1<<<130, 256>>>(g1b, g1s, skw);         // split-K layer-1 + skip (FFMA2)
    k_grkan2<<<NBATCH, 128>>>(g2b, g2s, gws, gbs, gwv, gbv, skb, lng, lnb);
    k_main<<<512, 256, SM_BYTES>>>(x, tw, kb, ksp, out);  // dominant KAN GEMM (FFMA2)
}

// round 11
// speedup vs baseline: 1.4995x; 1.2520x over previous
#include <cuda_runtime.h>
#include <cuda_fp16.h>
#include <cstdint>

#define NB 8
#define NBATCH 64
#define SEQ 1024
#define DIM 64
#define UDIM 128
#define SIGDIM 4160   // 64 + 64*64
#define FSTR 12       // feature row stride (floats) for grkan1
#define NSPLIT 4      // k_sig sequence splits

#define NTILE 512     // 65536 rows / 128
#define NCH 9         // K chunks (576 / 64)
#define CK 64         // K per chunk (fp16)
#define BSTR 72       // smem row stride in halves (144B -> conflict-free frags)

// ---------------- device scratch (no allocations allowed) ----------------
__device__ float g_sig[NBATCH * SIGDIM];
__device__ float g_part[NBATCH * NSPLIT * SIGDIM];
__device__ float g_hacc[NBATCH * UDIM];
__device__ float g_skip[NBATCH * UDIM];
__device__ float g_h2[NBATCH * UDIM];
__device__ float g_wts[NBATCH * UDIM];
// fp16 KAN features: [tile][chunk][row(128)][kk(64)]  (75 MB)
__device__ __align__(16) __half g_feat[(size_t)NTILE * NCH * 128 * CK];
// fp16 split weights: [chunk][u(128)][kk(64)]
__device__ __align__(16) __half g_bhi[NCH * 128 * CK];
__device__ __align__(16) __half g_blo[NCH * 128 * CK];

// ---------------- helpers ----------------
__device__ __forceinline__ float siluf(float x) { return x / (1.f + __expf(-x)); }
__device__ __forceinline__ float sigm(float x) { return 1.f / (1.f + __expf(-x)); }

__device__ __forceinline__ void ffma2(unsigned long long& acc,
                                      unsigned long long f,
                                      unsigned long long w) {
    asm("fma.rn.f32x2 %0, %1, %2, %0;" : "+l"(acc) : "l"(f), "l"(w));
}
__device__ __forceinline__ unsigned long long dup2(float f) {
    unsigned long long d;
    unsigned int u = __float_as_uint(f);
    asm("mov.b64 %0, {%1, %1};" : "=l"(d) : "r"(u));
    return d;
}
__device__ __forceinline__ unsigned long long pk2(float a, float b) {
    unsigned long long d;
    unsigned int ua = __float_as_uint(a), ub = __float_as_uint(b);
    asm("mov.b64 %0, {%1, %2};" : "=l"(d) : "r"(ua), "r"(ub));
    return d;
}

// warp-level HMMA: D[16x8] += A[16x16] * B[16x8], f16 in, f32 accum
__device__ __forceinline__ void mma16816(float* d, const uint32_t* a, const uint32_t* b) {
    asm volatile(
        "mma.sync.aligned.m16n8k16.row.col.f32.f16.f16.f32 "
        "{%0,%1,%2,%3}, {%4,%5,%6,%7}, {%8,%9}, {%0,%1,%2,%3};"
        : "+f"(d[0]), "+f"(d[1]), "+f"(d[2]), "+f"(d[3])
        : "r"(a[0]), "r"(a[1]), "r"(a[2]), "r"(a[3]), "r"(b[0]), "r"(b[1]));
}

// Cox-de Boor, order 3, uniform knots grid[i] = (i-3)*0.4 - 1 -> 8 bases
__device__ __forceinline__ void bspl8(float x, float* o) {
    float b[11];
#pragma unroll
    for (int i = 0; i < 11; i++) {
        float g0 = (i - 3) * 0.4f - 1.0f;
        float g1 = (i - 2) * 0.4f - 1.0f;
        b[i] = (x >= g0 && x < g1) ? 1.f : 0.f;
    }
#pragma unroll
    for (int p = 1; p <= 3; p++) {
        float inv = 1.f / (0.4f * (float)p);
#pragma unroll
        for (int i = 0; i + p < 11; i++) {
            float gi  = (i - 3) * 0.4f - 1.0f;
            float gip = (i + p - 2) * 0.4f - 1.0f;
            b[i] = (x - gi) * inv * b[i] + (gip - x) * inv * b[i + 1];
        }
    }
#pragma unroll
    for (int i = 0; i < 8; i++) o[i] = b[i];
}

// ---------------- K0a: feature generation (fp16) ----------------
__global__ __launch_bounds__(256) void k_feat(const float* __restrict__ x,
                                              const float* __restrict__ tw) {
    __shared__ __align__(16) __half fs[32][584];   // 32 rows x 576 features (+pad)

    const int tid = threadIdx.x;
    const int rg0 = blockIdx.x * 32;          // 32 rows per block (never crosses tile)

#pragma unroll
    for (int q = 0; q < 8; q++) {
        int idx = tid + q * 256;
        int r = idx >> 6, d = idx & 63;
        int rgl = rg0 + r;
        int s = rgl & (SEQ - 1);
        float xv = tw[s] * x[(size_t)rgl * DIM + d];
        float f[9];
        f[0] = siluf(xv);
        bspl8(xv, f + 1);
#pragma unroll
        for (int k = 0; k < 9; k++)
            fs[r][d * 9 + k] = __float2half_rn(f[k]);
    }
    __syncthreads();

    const int tile = rg0 >> 7;
#pragma unroll
    for (int q = 0; q < 9; q++) {
        int idx = tid + q * 256;              // 2304 16B pieces
        int p = idx >> 3, sub = idx & 7;
        int r = p / 9, c = p - r * 9;
        int rgl = rg0 + r;
        int rowin = rgl & 127;
        uint4 v = *(const uint4*)&fs[r][c * 64 + sub * 8];
        __half* dst = g_feat + ((size_t)(tile * 9 + c) * 128 + rowin) * CK + sub * 8;
        *(uint4*)dst = v;
    }
}

// ---------------- K0b: weight split hi/lo fp16 ----------------
__global__ __launch_bounds__(256) void k_wsplit(const float* __restrict__ kb,
                                                const float* __restrict__ ksp) {
    int idx = blockIdx.x * 256 + threadIdx.x;   // 288*256 == 9*128*64
    int kk = idx & 63, u = (idx >> 6) & 127, c = idx >> 13;
    int K = c * 64 + kk;
    int d = K / 9, kf = K - d * 9;
    float w = (kf == 0) ? kb[d * UDIM + u] : ksp[(d * NB + kf - 1) * UDIM + u];
    __half hi = __float2half_rn(w);
    g_bhi[idx] = hi;
    g_blo[idx] = __float2half_rn(w - __half2float(hi));
}

// ---------------- K1a: partial path signature ----------------
__global__ __launch_bounds__(256) void k_sig_part(const float* __restrict__ x,
                                                  const float* __restrict__ tw) {
    __shared__ __align__(16) float Ush[64 * 68];
    __shared__ __align__(16) float Qsh[64 * 68];
    __shared__ float segsum[4][64];
    __shared__ float carry[64];

    const int b = blockIdx.x >> 2;
    const int part = blockIdx.x & 3;
    const int tid = threadIdx.x;

    const int tstart = part * 256;
    const int tend = min(tstart + 256, SEQ - 1);

    const int d = tid & 63, seg = tid >> 6;
    if (tid < 64) carry[tid] = 0.f;

    unsigned long long acc2[4][2];
#pragma unroll
    for (int a = 0; a < 4; a++) { acc2[a][0] = 0ull; acc2[a][1] = 0ull; }

    const int i0 = (tid & 15) * 4;
    const int j0 = (tid >> 4) * 4;
    const float* xb = x + (size_t)b * SEQ * DIM;

    for (int t0 = tstart; t0 < tend; t0 += 64) {
        const int T = min(64, tend - t0);
        __syncthreads();

        for (int idx = tid; idx < T * 64; idx += 256) {
            int t = idx >> 6, dd = idx & 63;
            int gt = t0 + t;
            Ush[t * 68 + dd] = tw[gt + 1] * xb[(gt + 1) * DIM + dd]
                             - tw[gt]     * xb[gt * DIM + dd];
        }
        __syncthreads();

        const int ss = seg * 16;
        const int se = min(ss + 16, T);
        float ssum = 0.f;
        for (int t = ss; t < se; t++) ssum += Ush[t * 68 + d];
        segsum[seg][d] = ssum;
        __syncthreads();
        float off = carry[d];
        for (int s = 0; s < seg; s++) off += segsum[s][d];
        __syncthreads();
        float p = off;
        for (int t = ss; t < se; t++) {
            float u = Ush[t * 68 + d];
            Qsh[t * 68 + d] = p + 0.5f * u;
            p += u;
        }
        if (seg == 3) carry[d] = p;
        __syncthreads();

        for (int k = 0; k < T; k++) {
            float4 q  = *(const float4*)&Qsh[k * 68 + i0];
            float4 u4 = *(const float4*)&Ush[k * 68 + j0];
            unsigned long long uxy = pk2(u4.x, u4.y);
            unsigned long long uzw = pk2(u4.z, u4.w);
            unsigned long long q0 = dup2(q.x), q1 = dup2(q.y),
                               q2 = dup2(q.z), q3 = dup2(q.w);
            ffma2(acc2[0][0], q0, uxy); ffma2(acc2[0][1], q0, uzw);
            ffma2(acc2[1][0], q1, uxy); ffma2(acc2[1][1], q1, uzw);
            ffma2(acc2[2][0], q2, uxy); ffma2(acc2[2][1], q2, uzw);
            ffma2(acc2[3][0], q3, uxy); ffma2(acc2[3][1], q3, uzw);
        }
    }
    __syncthreads();

    float* pb = g_part + (size_t)(b * NSPLIT + part) * SIGDIM;
#pragma unroll
    for (int a = 0; a < 4; a++) {
        float2 lo = *(float2*)&acc2[a][0];
        float2 hi = *(float2*)&acc2[a][1];
        float4 v = make_float4(lo.x, lo.y, hi.x, hi.y);
        *(float4*)&pb[64 + (i0 + a) * 64 + j0] = v;
    }
    if (tid < 64) pb[tid] = carry[tid];
}

// ---------------- K1b: Chen combine ----------------
__global__ __launch_bounds__(256) void k_sig_combine() {
    __shared__ float s1[NSPLIT][64];
    __shared__ float pre[NSPLIT][64];

    const int b = blockIdx.x, tid = threadIdx.x;

    {   // zero GRKAN accumulators + h2
        int g = b * 256 + tid;
        if (g < NBATCH * UDIM) g_hacc[g] = 0.f;
        else g_skip[g - NBATCH * UDIM] = 0.f;
        if (tid < UDIM) g_h2[b * UDIM + tid] = 0.f;
    }

    if (tid < 64) {
        float acc = 0.f;
#pragma unroll
        for (int p = 0; p < NSPLIT; p++) {
            float v = g_part[(size_t)(b * NSPLIT + p) * SIGDIM + tid];
            s1[p][tid] = v;
            pre[p][tid] = acc;
            acc += v;
        }
        g_sig[(size_t)b * SIGDIM + tid] = acc;
    }
    __syncthreads();

    const int i0 = (tid & 15) * 4;
    const int j0 = (tid >> 4) * 4;

    float acc[4][4];
#pragma unroll
    for (int a = 0; a < 4; a++)
#pragma unroll
        for (int c = 0; c < 4; c++) acc[a][c] = 0.f;

#pragma unroll
    for (int p = 0; p < NSPLIT; p++) {
        const float* s2p = g_part + (size_t)(b * NSPLIT + p) * SIGDIM + 64;
        float4 s1j = *(const float4*)&s1[p][j0];
#pragma unroll
        for (int a = 0; a < 4; a++) {
            float4 v = *(const float4*)&s2p[(i0 + a) * 64 + j0];
            float pi = pre[p][i0 + a];
            acc[a][0] += v.x + pi * s1j.x;
            acc[a][1] += v.y + pi * s1j.y;
            acc[a][2] += v.z + pi * s1j.z;
            acc[a][3] += v.w + pi * s1j.w;
        }
    }

    float* sb = g_sig + (size_t)b * SIGDIM;
#pragma unroll
    for (int a = 0; a < 4; a++) {
        float4 v = make_float4(acc[a][0], acc[a][1], acc[a][2], acc[a][3]);
        *(float4*)&sb[64 + (i0 + a) * 64 + j0] = v;
    }
}

// ---------------- K2: GRKAN layer 1 + skip (FFMA2) ----------------
__global__ __launch_bounds__(256, 2) void k_grkan1(const float* __restrict__ g1b,
                                                   const float* __restrict__ g1s,
                                                   const float* __restrict__ skw) {
    __shared__ __align__(16) float st[64 * 33];
    __shared__ __align__(16) float fb[2 * 64 * FSTR];
    __shared__ __align__(16) float wb[2 * 10 * 128];

    const int tid = threadIdx.x;
    const int in0 = blockIdx.x * 32;

    for (int idx = tid; idx < 64 * 32; idx += 256) {
        int bb = idx >> 5, i = idx & 31;
        st[bb * 33 + i] = g_sig[(size_t)bb * SIGDIM + in0 + i];
    }

    unsigned long long ah2[4][4], as2[4][4];
#pragma unroll
    for (int i = 0; i < 4; i++)
#pragma unroll
        for (int j = 0; j < 4; j++) { ah2[i][j] = 0ull; as2[i][j] = 0ull; }

    const int cg = tid & 15, rg = tid >> 4;
    const int c0 = cg * 8, r0 = rg * 4;

    for (int dl = 0; dl < 32; dl += 2) {
        __syncthreads();
        if (tid < 128) {
            int bb = tid & 63, dp = tid >> 6;
            float xv = st[bb * 33 + dl + dp];
            float f[12];
            f[0] = siluf(xv);
            bspl8(xv, f + 1);
            f[9] = xv;
            f[10] = 0.f; f[11] = 0.f;
            float* fr = &fb[(dp * 64 + bb) * FSTR];
            *(float4*)&fr[0] = *(float4*)&f[0];
            *(float4*)&fr[4] = *(float4*)&f[4];
            *(float4*)&fr[8] = *(float4*)&f[8];
        }
        for (int idx = tid; idx < 2560; idx += 256) {
            int c = idx & 127, row = idx >> 7;
            int dp = row / 10, k = row - dp * 10;
            int in = in0 + dl + dp;
            float w;
            if (k == 0) w = g1b[in * UDIM + c];
            else if (k < 9) w = g1s[(in * NB + (k - 1)) * UDIM + c];
            else w = skw[in * UDIM + c];
            wb[row * 128 + c] = w;
        }
        __syncthreads();

#pragma unroll
        for (int dp = 0; dp < 2; dp++) {
#pragma unroll
            for (int g = 0; g < 2; g++) {
                ulonglong2 w0a, w0c, w1a, w1c, w2a, w2c, w3a, w3c;
                {
                    const float* wr0 = &wb[(dp * 10 + 4 * g + 0) * 128 + c0];
                    const float* wr1 = &wb[(dp * 10 + 4 * g + 1) * 128 + c0];
                    const float* wr2 = &wb[(dp * 10 + 4 * g + 2) * 128 + c0];
                    const float* wr3 = &wb[(dp * 10 + 4 * g + 3) * 128 + c0];
                    w0a = *(const ulonglong2*)wr0; w0c = *(const ulonglong2*)(wr0 + 4);
                    w1a = *(const ulonglong2*)wr1; w1c = *(const ulonglong2*)(wr1 + 4);
                    w2a = *(const ulonglong2*)wr2; w2c = *(const ulonglong2*)(wr2 + 4);
                    w3a = *(const ulonglong2*)wr3; w3c = *(const ulonglong2*)(wr3 + 4);
                }
#pragma unroll
                for (int i = 0; i < 4; i++) {
                    float4 f4 = *(const float4*)&fb[(dp * 64 + r0 + i) * FSTR + 4 * g];
                    unsigned long long fx = dup2(f4.x), fy = dup2(f4.y),
                                       fz = dup2(f4.z), fw = dup2(f4.w);
                    ffma2(ah2[i][0], fx, w0a.x); ffma2(ah2[i][1], fx, w0a.y);
                    ffma2(ah2[i][2], fx, w0c.x); ffma2(ah2[i][3], fx, w0c.y);
                    ffma2(ah2[i][0], fy, w1a.x); ffma2(ah2[i][1], fy, w1a.y);
                    ffma2(ah2[i][2], fy, w1c.x); ffma2(ah2[i][3], fy, w1c.y);
                    ffma2(ah2[i][0], fz, w2a.x); ffma2(ah2[i][1], fz, w2a.y);
                    ffma2(ah2[i][2], fz, w2c.x); ffma2(ah2[i][3], fz, w2c.y);
                    ffma2(ah2[i][0], fw, w3a.x); ffma2(ah2[i][1], fw, w3a.y);
                    ffma2(ah2[i][2], fw, w3c.x); ffma2(ah2[i][3], fw, w3c.y);
                }
            }
            {
                const float* wr8 = &wb[(dp * 10 + 8) * 128 + c0];
                const float* wr9 = &wb[(dp * 10 + 9) * 128 + c0];
                ulonglong2 w8a = *(const ulonglong2*)wr8, w8c = *(const ulonglong2*)(wr8 + 4);
                ulonglong2 w9a = *(const ulonglong2*)wr9, w9c = *(const ulonglong2*)(wr9 + 4);
#pragma unroll
                for (int i = 0; i < 4; i++) {
                    float2 ft = *(const float2*)&fb[(dp * 64 + r0 + i) * FSTR + 8];
                    unsigned long long f8 = dup2(ft.x), f9 = dup2(ft.y);
                    ffma2(ah2[i][0], f8, w8a.x); ffma2(ah2[i][1], f8, w8a.y);
                    ffma2(ah2[i][2], f8, w8c.x); ffma2(ah2[i][3], f8, w8c.y);
                    ffma2(as2[i][0], f9, w9a.x); ffma2(as2[i][1], f9, w9a.y);
                    ffma2(as2[i][2], f9, w9c.x); ffma2(as2[i][3], f9, w9c.y);
                }
            }
        }
    }

#pragma unroll
    for (int i = 0; i < 4; i++)
#pragma unroll
        for (int j = 0; j < 4; j++) {
            float2 h = *(float2*)&ah2[i][j];
            float2 s = *(float2*)&as2[i][j];
            atomicAdd(&g_hacc[(r0 + i) * UDIM + c0 + 2 * j],     h.x);
            atomicAdd(&g_hacc[(r0 + i) * UDIM + c0 + 2 * j + 1], h.y);
            atomicAdd(&g_skip[(r0 + i) * UDIM + c0 + 2 * j],     s.x);
            atomicAdd(&g_skip[(r0 + i) * UDIM + c0 + 2 * j + 1], s.y);
        }
}

// ---------------- K3a: GRKAN layer 2 GEMM, split over v-slices ----------------
__global__ __launch_bounds__(128) void k_h2(const float* __restrict__ g2b,
                                            const float* __restrict__ g2s) {
    __shared__ float f[16][10];
    const int b = blockIdx.x >> 3, sl = blockIdx.x & 7;
    const int v0 = sl * 16;
    const int tid = threadIdx.x;

    if (tid < 16) {
        float hv = g_hacc[b * UDIM + v0 + tid];
        f[tid][0] = siluf(hv);
        bspl8(hv, &f[tid][1]);
    }
    __syncthreads();

    float acc = 0.f;
#pragma unroll 4
    for (int vv = 0; vv < 16; vv++) {
        int v = v0 + vv;
        const float* fr = f[vv];
        acc += fr[0] * g2b[v * UDIM + tid];
#pragma unroll
        for (int k = 0; k < 8; k++)
            acc += fr[1 + k] * g2s[(v * NB + k) * UDIM + tid];
    }
    atomicAdd(&g_h2[b * UDIM + tid], acc);
}

// ---------------- K3b: gate + layernorm + softmax ----------------
__global__ __launch_bounds__(128) void k_gate(const float* __restrict__ gws,
                                              const float* __restrict__ gbs,
                                              const float* __restrict__ gwv,
                                              const float* __restrict__ gbv,
                                              const float* __restrict__ skb,
                                              const float* __restrict__ lng,
                                              const float* __restrict__ lnb) {
    __shared__ float h2s[128];
    __shared__ float red[4];

    const int b = blockIdx.x, u = threadIdx.x;

    auto blocksum = [&](float v) -> float {
#pragma unroll
        for (int o = 16; o; o >>= 1) v += __shfl_xor_sync(0xffffffffu, v, o);
        __syncthreads();
        if ((threadIdx.x & 31) == 0) red[threadIdx.x >> 5] = v;
        __syncthreads();
        return red[0] + red[1] + red[2] + red[3];
    };
    auto blockmax = [&](float v) -> float {
#pragma unroll
        for (int o = 16; o; o >>= 1) v = fmaxf(v, __shfl_xor_sync(0xffffffffu, v, o));
        __syncthreads();
        if ((threadIdx.x & 31) == 0) red[threadIdx.x >> 5] = v;
        __syncthreads();
        return fmaxf(fmaxf(red[0], red[1]), fmaxf(red[2], red[3]));
    };

    h2s[u] = g_h2[b * UDIM + u];
    __syncthreads();

    float gs = gbs[u], gv = gbv[u];
#pragma unroll 4
    for (int v = 0; v < 128; v++) {
        float hh = h2s[v];
        gs += hh * gws[v * UDIM + u];
        gv += hh * gwv[v * UDIM + u];
    }
    float sk = g_skip[b * UDIM + u] + skb[u];
    float pre = sk + sigm(gs) * gv;

    float s1 = blocksum(pre);
    float s2 = blocksum(pre * pre);
    float mu = s1 * (1.f / 128.f);
    float var = s2 * (1.f / 128.f) - mu * mu;
    float y = lng[u] * (pre - mu) * rsqrtf(var + 1e-3f) + lnb[u];

    float m = blockmax(y);
    float e = __expf(y - m);
    float se = blocksum(e);
    g_wts[b * UDIM + u] = e / se;
}

// ---------------- K4: warp-MMA HGEMM over precomputed features ----------------
// out[row][u] = ( sum_c A_c[128x64] @ (Bhi_c + Blo_c)^T ) * wts[u]
#define SMB (3 * 128 * BSTR * 2)   // 55296 bytes

__global__ __launch_bounds__(256, 2) void k_main(float* __restrict__ out) {
    extern __shared__ __align__(16) __half sm[];
    __half* sA = sm;                   // A   128 x BSTR
    __half* sH = sm + 128 * BSTR;      // Bhi 128 x BSTR
    __half* sL = sm + 2 * 128 * BSTR;  // Blo 128 x BSTR
    __shared__ float s_wts[128];

    const int tid = threadIdx.x;
    const int w = tid >> 5, lane = tid & 31;
    const int tile = blockIdx.x;
    const int row0 = tile * 128;
    const int b = row0 >> 10;

    if (tid < 128) s_wts[tid] = g_wts[b * UDIM + tid];

    const int rbase = (w >> 2) * 64;   // warp row origin (0 / 64)
    const int cbase = (w & 3) * 32;    // warp col origin (0/32/64/96)
    const int g = lane >> 2, t = lane & 3;

    float acc[4][4][4];
#pragma unroll
    for (int mi = 0; mi < 4; mi++)
#pragma unroll
        for (int ni = 0; ni < 4; ni++)
#pragma unroll
            for (int q = 0; q < 4; q++) acc[mi][ni][q] = 0.f;

    for (int c = 0; c < NCH; c++) {
        __syncthreads();   // previous chunk's fragment loads done
        {
            const uint4* srcA = (const uint4*)(g_feat + (size_t)(tile * 9 + c) * 8192);
            const uint4* srcH = (const uint4*)(g_bhi + c * 8192);
            const uint4* srcL = (const uint4*)(g_blo + c * 8192);
#pragma unroll
            for (int q = 0; q < 4; q++) {
                int idx = tid + q * 256;        // 1024 16B pieces each
                int r = idx >> 3, sub = idx & 7;
                *(uint4*)(sA + r * BSTR + sub * 8) = srcA[idx];
                *(uint4*)(sH + r * BSTR + sub * 8) = srcH[idx];
                *(uint4*)(sL + r * BSTR + sub * 8) = srcL[idx];
            }
        }
        __syncthreads();

#pragma unroll
        for (int ks = 0; ks < 4; ks++) {        // K = 16 per step
            const int k0 = ks * 16;
            uint32_t a[4][4];
#pragma unroll
            for (int mi = 0; mi < 4; mi++) {
                const __half* ap = sA + (rbase + mi * 16 + g) * BSTR + k0;
                a[mi][0] = *(const uint32_t*)(ap + 2 * t);
                a[mi][1] = *(const uint32_t*)(ap + 8 * BSTR + 2 * t);
                a[mi][2] = *(const uint32_t*)(ap + 2 * t + 8);
                a[mi][3] = *(const uint32_t*)(ap + 8 * BSTR + 2 * t + 8);
            }
            uint32_t bh[4][2], bl[4][2];
#pragma unroll
            for (int ni = 0; ni < 4; ni++) {
                const __half* hp = sH + (cbase + ni * 8 + g) * BSTR + k0;
                const __half* lp = sL + (cbase + ni * 8 + g) * BSTR + k0;
                bh[ni][0] = *(const uint32_t*)(hp + 2 * t);
                bh[ni][1] = *(const uint32_t*)(hp + 2 * t + 8);
                bl[ni][0] = *(const uint32_t*)(lp + 2 * t);
                bl[ni][1] = *(const uint32_t*)(lp + 2 * t + 8);
            }
#pragma unroll
            for (int mi = 0; mi < 4; mi++)
#pragma unroll
                for (int ni = 0; ni < 4; ni++) {
                    mma16816(acc[mi][ni], a[mi], bh[ni]);
                    mma16816(acc[mi][ni], a[mi], bl[ni]);
                }
        }
    }

    // epilogue: multiply by softmax weights, store
#pragma unroll
    for (int ni = 0; ni < 4; ni++) {
        int col = cbase + ni * 8 + 2 * t;
        float w0 = s_wts[col], w1 = s_wts[col + 1];
#pragma unroll
        for (int mi = 0; mi < 4; mi++) {
            int r1 = row0 + rbase + mi * 16 + g;
            float2 o0 = make_float2(acc[mi][ni][0] * w0, acc[mi][ni][1] * w1);
            float2 o1 = make_float2(acc[mi][ni][2] * w0, acc[mi][ni][3] * w1);
            *(float2*)(out + (size_t)r1 * UDIM + col) = o0;
            *(float2*)(out + (size_t)(r1 + 8) * UDIM + col) = o1;
        }
    }
}

// ---------------- launch ----------------
extern "C" void kernel_launch(void* const* d_in, const int* in_sizes, int n_in,
                              void* d_out, int out_size) {
    const float* x   = (const float*)d_in[0];
    const float* tw  = (const float*)d_in[1];
    const float* kb  = (const float*)d_in[2];
    const float* ksp = (const float*)d_in[3];
    const float* g1b = (const float*)d_in[4];
    const float* g1s = (const float*)d_in[5];
    const float* g2b = (const float*)d_in[6];
    const float* g2s = (const float*)d_in[7];
    const float* skw = (const float*)d_in[8];
    const float* skb = (const float*)d_in[9];
    const float* gws = (const float*)d_in[10];
    const float* gbs = (const float*)d_in[11];
    const float* gwv = (const float*)d_in[12];
    const float* gbv = (const float*)d_in[13];
    const float* lng = (const float*)d_in[14];
    const float* lnb = (const float*)d_in[15];
    float* out = (float*)d_out;

    cudaFuncSetAttribute(k_main, cudaFuncAttributeMaxDynamicSharedMemorySize, SMB);

    k_feat<<<2048, 256>>>(x, tw);                  // fp16 KAN features -> g_feat
    k_wsplit<<<288, 256>>>(kb, ksp);               // fp16 hi/lo weight split
    k_sig_part<<<NBATCH * NSPLIT, 256>>>(x, tw);   // split signature partials
    k_sig_combine<<<NBATCH, 256>>>();              // Chen combine + zero accums
    k_grkan1<<<130, 256>>>(g1b, g1s, skw);         // layer-1 + skip (FFMA2)
    k_h2<<<NBATCH * 8, 128>>>(g2b, g2s);           // layer-2 GEMM (split-K)
    k_gate<<<NBATCH, 128>>>(gws, gbs, gwv, gbv, skb, lng, lnb);
    k_main<<<NTILE, 256, SMB>>>(out);              // warp-MMA HGEMM + weights
}